// round 4
// baseline (speedup 1.0000x reference)
#include <cuda_runtime.h>
#include <cstdint>
#include <math_constants.h>

#define TPB 256
#define NCTAS 296

__device__ unsigned int g_counter;

__global__ void init_counter_kernel() { g_counter = 0u; }

__device__ __forceinline__ unsigned long long pk2(float lo, float hi) {
    unsigned long long r;
    asm("mov.b64 %0, {%1, %2};" : "=l"(r) : "f"(lo), "f"(hi));
    return r;
}
__device__ __forceinline__ void upk2(unsigned long long v, float& lo, float& hi) {
    asm("mov.b64 {%0, %1}, %2;" : "=f"(lo), "=f"(hi) : "l"(v));
}
// Packed fp32x2 FMA (Blackwell): per-lane IEEE rn FMA, identical rounding to scalar fmaf.
__device__ __forceinline__ unsigned long long ffma2(unsigned long long a,
                                                    unsigned long long b,
                                                    unsigned long long c) {
    unsigned long long d;
    asm("fma.rn.f32x2 %0, %1, %2, %3;" : "=l"(d) : "l"(a), "l"(b), "l"(c));
    return d;
}

// Recompute the packed score chain for candidate q — must be bit-identical to
// the main loop (same ffma2 sequence).
__device__ __forceinline__ unsigned long long score2(const ulonglong2* __restrict__ srec,
                                                     const unsigned long long* ya,
                                                     unsigned long long ZERO,
                                                     unsigned long long TWO, int q) {
    const ulonglong2* gpt = srec + (size_t)q * 5;
    ulonglong2 g01 = gpt[0], g23 = gpt[1], g45 = gpt[2], g67 = gpt[3];
    unsigned long long nn = gpt[4].x;
    unsigned long long acc = ffma2(g01.x, ya[0], ZERO);
    acc = ffma2(g01.y, ya[1], acc);
    acc = ffma2(g23.x, ya[2], acc);
    acc = ffma2(g23.y, ya[3], acc);
    acc = ffma2(g45.x, ya[4], acc);
    acc = ffma2(g45.y, ya[5], acc);
    acc = ffma2(g67.x, ya[6], acc);
    acc = ffma2(g67.y, ya[7], acc);
    return ffma2(TWO, acc, nn);
}

// Find first q in block blk whose selected lane equals target (bit-exact rescan).
__device__ __forceinline__ int rescan_block(const ulonglong2* __restrict__ srec,
                                            const unsigned long long* ya,
                                            unsigned long long ZERO,
                                            unsigned long long TWO,
                                            float target, int blk, int lane_hi) {
    int found = -1;
    int q0 = blk << 5;
    for (int qq = 0; qq < 32; qq++) {
        unsigned long long s2 = score2(srec, ya, ZERO, TWO, q0 + qq);
        float sp, sm;
        upk2(s2, sp, sm);
        float v = lane_hi ? sm : sp;
        if (found < 0 && v == target) found = q0 + qq;
    }
    return found;
}

__global__ __launch_bounds__(TPB, 2) void e8p_kernel(
    const float* __restrict__ X,
    const float* __restrict__ grid,       // [n_grid, 8]
    const float* __restrict__ gnorm,      // [n_grid]
    const int*   __restrict__ allcombo,   // [128, n_grid]
    const int*   __restrict__ idx_map,    // [256]
    float* __restrict__ out,
    int N, int n_grid, int ngp, int idx_mode)
{
    // Candidate record: 5 ulonglong2 = 80 B:
    //   [0..3] = (g0,g0),(g1,g1) | ... | (g6,g6),(g7,g7)
    //   [4].x  = (-norm,-norm); sentinel records (q >= n_grid): g=0, nn=-inf.
    extern __shared__ ulonglong2 srec[];
    int* simap = (int*)(srec + (size_t)ngp * 5);   // [256]

    for (int q = threadIdx.x; q < ngp; q += TPB) {
        ulonglong2* r = srec + (size_t)q * 5;
        if (q < n_grid) {
            const float* g = grid + (size_t)q * 8;
            #pragma unroll
            for (int p = 0; p < 4; p++)
                r[p] = make_ulonglong2(pk2(g[2 * p], g[2 * p]),
                                       pk2(g[2 * p + 1], g[2 * p + 1]));
            float nn = -gnorm[q];
            r[4] = make_ulonglong2(pk2(nn, nn), 0ull);
        } else {
            #pragma unroll
            for (int p = 0; p < 4; p++) r[p] = make_ulonglong2(0ull, 0ull);
            r[4] = make_ulonglong2(pk2(-CUDART_INF_F, -CUDART_INF_F), 0ull);
        }
    }
    if (threadIdx.x < 256) simap[threadIdx.x] = idx_map[threadIdx.x];
    __syncthreads();

    const int nchunks = N >> 6;          // 64 rows per chunk (2 per lane)
    const int nblocks = ngp >> 5;        // 32 candidates per block
    const int lane = threadIdx.x & 31;
    const unsigned long long ZERO = pk2(0.0f, 0.0f);
    const unsigned long long TWO  = pk2(2.0f, 2.0f);
    const float* sgf = (const float*)srec;   // g_j of candidate q at sgf[q*20 + j*2]

    while (true) {
        unsigned c;
        if (lane == 0) c = atomicAdd(&g_counter, 1u);
        c = __shfl_sync(0xFFFFFFFFu, c, 0);
        if (c >= (unsigned)nchunks) break;
        const int base = (int)(c << 6);
        int rows[2] = {base + lane, base + 32 + lane};

        unsigned negp[2], negm[2], pp[2], pm[2];
        unsigned long long ya[2][8];

        #pragma unroll
        for (int r = 0; r < 2; r++) {
            const float4* X4 = (const float4*)(X + (size_t)rows[r] * 8);
            float4 xa = X4[0], xb = X4[1];
            float xr[8] = {xa.x, xa.y, xa.z, xa.w, xb.x, xb.y, xb.z, xb.w};

            unsigned np = 0u, nm = 0u;
            float ap[8], am[8];
            #pragma unroll
            for (int j = 0; j < 8; j++) {
                float yp = __fadd_rn(xr[j], 0.25f);
                float ym = __fsub_rn(xr[j], 0.25f);
                if (yp < 0.0f) np |= 1u << j;
                if (ym < 0.0f) nm |= 1u << j;
                ap[j] = fabsf(yp);
                am[j] = fabsf(ym);
            }
            pp[r] = __popc(np) & 1u;
            pm[r] = __popc(nm) & 1u;
            negp[r] = np; negm[r] = nm;
            if (pp[r]) ap[0] = -ap[0];
            if (pm[r]) am[0] = -am[0];
            #pragma unroll
            for (int j = 0; j < 8; j++) ya[r][j] = pk2(ap[j], am[j]);
        }

        // Block-max scan: no index tracking in the hot loop.
        float gbP[2] = {-CUDART_INF_F, -CUDART_INF_F};
        float gbM[2] = {-CUDART_INF_F, -CUDART_INF_F};
        int blkP[2] = {0, 0}, blkM[2] = {0, 0};

        for (int b = 0; b < nblocks; b++) {
            float mPA[2] = {-CUDART_INF_F, -CUDART_INF_F};
            float mPB[2] = {-CUDART_INF_F, -CUDART_INF_F};
            float mMA[2] = {-CUDART_INF_F, -CUDART_INF_F};
            float mMB[2] = {-CUDART_INF_F, -CUDART_INF_F};
            const int q0 = b << 5;
            #pragma unroll 4
            for (int qq = 0; qq < 32; qq++) {
                const ulonglong2* gpt = srec + (size_t)(q0 + qq) * 5;
                ulonglong2 g01 = gpt[0], g23 = gpt[1], g45 = gpt[2], g67 = gpt[3];
                unsigned long long nn = gpt[4].x;

                #pragma unroll
                for (int r = 0; r < 2; r++) {
                    unsigned long long acc = ffma2(g01.x, ya[r][0], ZERO);
                    acc = ffma2(g01.y, ya[r][1], acc);
                    acc = ffma2(g23.x, ya[r][2], acc);
                    acc = ffma2(g23.y, ya[r][3], acc);
                    acc = ffma2(g45.x, ya[r][4], acc);
                    acc = ffma2(g45.y, ya[r][5], acc);
                    acc = ffma2(g67.x, ya[r][6], acc);
                    acc = ffma2(g67.y, ya[r][7], acc);
                    unsigned long long s2 = ffma2(TWO, acc, nn);
                    float sp, sm;
                    upk2(s2, sp, sm);
                    if (qq & 1) {
                        mPB[r] = fmaxf(mPB[r], sp);
                        mMB[r] = fmaxf(mMB[r], sm);
                    } else {
                        mPA[r] = fmaxf(mPA[r], sp);
                        mMA[r] = fmaxf(mMA[r], sm);
                    }
                }
            }
            #pragma unroll
            for (int r = 0; r < 2; r++) {
                float bp = fmaxf(mPA[r], mPB[r]);
                float bm = fmaxf(mMA[r], mMB[r]);
                if (bp > gbP[r]) { gbP[r] = bp; blkP[r] = b; }
                if (bm > gbM[r]) { gbM[r] = bm; blkM[r] = b; }
            }
        }

        // Epilogue per row: rescan winning blocks, then exact residual compare.
        #pragma unroll
        for (int r = 0; r < 2; r++) {
            const int qp = rescan_block(srec, ya[r], ZERO, TWO, gbP[r], blkP[r], 0);
            const int qm = rescan_block(srec, ya[r], ZERO, TWO, gbM[r], blkM[r], 1);

            const unsigned mnegp = negp[r] ^ pp[r];   // parity flips bit 0
            const unsigned mnegm = negm[r] ^ pm[r];
            float e2p = 0.0f, e2m = 0.0f;
            #pragma unroll
            for (int j = 0; j < 8; j++) {
                float apj, amj;
                upk2(ya[r][j], apj, amj);
                float yp = ((negp[r] >> j) & 1u) ? -fabsf(apj) : fabsf(apj);
                float ym = ((negm[r] >> j) & 1u) ? -fabsf(amj) : fabsf(amj);
                float gp_ = sgf[qp * 20 + j * 2];
                float gm_ = sgf[qm * 20 + j * 2];
                float vpj = ((mnegp >> j) & 1u) ? -gp_ : gp_;
                float vmj = ((mnegm >> j) & 1u) ? -gm_ : gm_;
                float dp = __fsub_rn(yp, vpj);
                float dm = __fsub_rn(ym, vmj);
                e2p = __fadd_rn(e2p, __fmul_rn(dp, dp));
                e2m = __fadd_rn(e2m, __fmul_rn(dm, dm));
            }
            const bool which = __fsqrt_rn(e2p) < __fsqrt_rn(e2m);

            const int q = which ? qp : qm;
            const unsigned mneg = which ? mnegp : mnegm;
            const unsigned negs = which ? negp[r] : negm[r];
            const float delta = which ? -0.25f : 0.25f;

            const int mint = (int)(__brev(mneg & 0xFFu) >> 24);  // bit j -> 2^(7-j)
            const int r128 = simap[mint];
            const int ridx = __ldg(&allcombo[(size_t)r128 * n_grid + q]);
            const int fidx = which ? ridx : (ridx - 32768);
            (void)negs;

            float v[8];
            #pragma unroll
            for (int j = 0; j < 8; j++) {
                float g = sgf[q * 20 + j * 2];
                float sg = ((mneg >> j) & 1u) ? -g : g;    // grid*mask (exact)
                v[j] = __fadd_rn(sg, delta);               // fl(vals -/+ 0.25)
            }
            float4* O = (float4*)(out + (size_t)rows[r] * 8);
            O[0] = make_float4(v[0], v[1], v[2], v[3]);
            O[1] = make_float4(v[4], v[5], v[6], v[7]);

            if (idx_mode == 1) {
                out[(size_t)N * 8 + rows[r]] = (float)fidx;
            } else if (idx_mode == 2) {
                ((short*)(out + (size_t)N * 8))[rows[r]] = (short)fidx;
            }
        }
    }
}

extern "C" void kernel_launch(void* const* d_in, const int* in_sizes, int n_in,
                              void* d_out, int out_size) {
    const float* X        = (const float*)d_in[0];
    const float* grid     = (const float*)d_in[1];
    const float* gnorm    = (const float*)d_in[2];
    const int*   allcombo = (const int*)d_in[3];
    const int*   idx_map  = (const int*)d_in[4];

    const int N = in_sizes[0] / 8;
    const int n_grid = in_sizes[2];
    const int ngp = (n_grid + 31) & ~31;     // pad to block multiple with sentinels

    int idx_mode = 0;
    if (out_size >= N * 9) idx_mode = 1;                     // idx stored as floats
    else if (out_size >= N * 8 + (N + 1) / 2) idx_mode = 2;  // idx packed as int16

    size_t smem_bytes = (size_t)ngp * 80 + 1024 + 64;
    cudaFuncSetAttribute(e8p_kernel, cudaFuncAttributeMaxDynamicSharedMemorySize,
                         (int)smem_bytes);

    init_counter_kernel<<<1, 1>>>();
    e8p_kernel<<<NCTAS, TPB, smem_bytes>>>(X, grid, gnorm, allcombo, idx_map,
                                           (float*)d_out, N, n_grid, ngp, idx_mode);
}

// round 6
// speedup vs baseline: 1.1382x; 1.1382x over previous
#include <cuda_runtime.h>
#include <cstdint>
#include <math_constants.h>

#define TPB 256
#define NCTAS 296
#define R 3                      // rows per lane

__device__ unsigned int g_counter;

__global__ void init_counter_kernel() { g_counter = 0u; }

__device__ __forceinline__ unsigned long long pk2(float lo, float hi) {
    unsigned long long r;
    asm("mov.b64 %0, {%1, %2};" : "=l"(r) : "f"(lo), "f"(hi));
    return r;
}
__device__ __forceinline__ void upk2(unsigned long long v, float& lo, float& hi) {
    asm("mov.b64 {%0, %1}, %2;" : "=f"(lo), "=f"(hi) : "l"(v));
}
// Packed fp32x2 FMA (Blackwell): per-lane IEEE rn FMA, identical rounding to scalar fmaf.
__device__ __forceinline__ unsigned long long ffma2(unsigned long long a,
                                                    unsigned long long b,
                                                    unsigned long long c) {
    unsigned long long d;
    asm("fma.rn.f32x2 %0, %1, %2, %3;" : "=l"(d) : "l"(a), "l"(b), "l"(c));
    return d;
}

__global__ __launch_bounds__(TPB, 2) void e8p_kernel(
    const float* __restrict__ X,
    const float* __restrict__ grid,       // [n_grid, 8]
    const float* __restrict__ gnorm,      // [n_grid]
    const int*   __restrict__ allcombo,   // [128, n_grid]
    const int*   __restrict__ idx_map,    // [256]
    float* __restrict__ out,
    int N, int n_grid, int idx_mode)
{
    // Candidate record: 5 ulonglong2 = 80 B:
    //   [0..3] = (g0,g0),(g1,g1) | (g2,g2),(g3,g3) | (g4,g4),(g5,g5) | (g6,g6),(g7,g7)
    //   [4].x  = (-norm,-norm). One sentinel record appended for the pipeline preload.
    extern __shared__ ulonglong2 srec[];
    int* simap = (int*)(srec + (size_t)(n_grid + 1) * 5);   // [256]

    for (int q = threadIdx.x; q < n_grid + 1; q += TPB) {
        ulonglong2* rrec = srec + (size_t)q * 5;
        if (q < n_grid) {
            const float* g = grid + (size_t)q * 8;
            #pragma unroll
            for (int p = 0; p < 4; p++)
                rrec[p] = make_ulonglong2(pk2(g[2 * p], g[2 * p]),
                                          pk2(g[2 * p + 1], g[2 * p + 1]));
            float nn = -gnorm[q];
            rrec[4] = make_ulonglong2(pk2(nn, nn), 0ull);
        } else {
            #pragma unroll
            for (int p = 0; p < 4; p++) rrec[p] = make_ulonglong2(0ull, 0ull);
            rrec[4] = make_ulonglong2(pk2(-CUDART_INF_F, -CUDART_INF_F), 0ull);
        }
    }
    if (threadIdx.x < 256) simap[threadIdx.x] = idx_map[threadIdx.x];
    __syncthreads();

    const int rows_per_chunk = 32 * R;
    const int nchunks = (N + rows_per_chunk - 1) / rows_per_chunk;
    const int lane = threadIdx.x & 31;
    const unsigned long long ZERO = pk2(0.0f, 0.0f);
    const unsigned long long TWO  = pk2(2.0f, 2.0f);
    const float* sgf = (const float*)srec;   // g_j of candidate q at sgf[q*20 + j*2]

    while (true) {
        unsigned c;
        if (lane == 0) c = atomicAdd(&g_counter, 1u);
        c = __shfl_sync(0xFFFFFFFFu, c, 0);
        if (c >= (unsigned)nchunks) break;
        const int base = (int)c * rows_per_chunk;

        int rows[R];
        bool valid[R];
        unsigned negp[R], negm[R], pp[R], pm[R];
        unsigned long long ya[R][8];

        #pragma unroll
        for (int r = 0; r < R; r++) {
            rows[r] = base + 32 * r + lane;
            valid[r] = rows[r] < N;
            int lrow = valid[r] ? rows[r] : (N - 1);
            const float4* X4 = (const float4*)(X + (size_t)lrow * 8);
            float4 xa = X4[0], xb = X4[1];
            float xr[8] = {xa.x, xa.y, xa.z, xa.w, xb.x, xb.y, xb.z, xb.w};

            unsigned np = 0u, nm = 0u;
            float ap[8], am[8];
            #pragma unroll
            for (int j = 0; j < 8; j++) {
                float yp = __fadd_rn(xr[j], 0.25f);
                float ym = __fsub_rn(xr[j], 0.25f);
                if (yp < 0.0f) np |= 1u << j;
                if (ym < 0.0f) nm |= 1u << j;
                ap[j] = fabsf(yp);
                am[j] = fabsf(ym);
            }
            pp[r] = __popc(np) & 1u;
            pm[r] = __popc(nm) & 1u;
            negp[r] = np; negm[r] = nm;
            if (pp[r]) ap[0] = -ap[0];
            if (pm[r]) am[0] = -am[0];
            #pragma unroll
            for (int j = 0; j < 8; j++) ya[r][j] = pk2(ap[j], am[j]);
        }

        float bsp[R], bsm[R];
        int qp[R], qm[R];
        #pragma unroll
        for (int r = 0; r < R; r++) {
            bsp[r] = -CUDART_INF_F; bsm[r] = -CUDART_INF_F;
            qp[r] = 0; qm[r] = 0;
        }

        // Manual 1-deep software pipeline: load record q+1 while scoring q.
        ulonglong2 g01 = srec[0], g23 = srec[1], g45 = srec[2], g67 = srec[3];
        unsigned long long nn = srec[4].x;

        for (int q = 0; q < n_grid; q++) {
            const ulonglong2* gnx = srec + (size_t)(q + 1) * 5;
            ulonglong2 n01 = gnx[0], n23 = gnx[1], n45 = gnx[2], n67 = gnx[3];
            unsigned long long nnn = gnx[4].x;

            #pragma unroll
            for (int r = 0; r < R; r++) {
                unsigned long long acc = ffma2(g01.x, ya[r][0], ZERO);
                acc = ffma2(g01.y, ya[r][1], acc);
                acc = ffma2(g23.x, ya[r][2], acc);
                acc = ffma2(g23.y, ya[r][3], acc);
                acc = ffma2(g45.x, ya[r][4], acc);
                acc = ffma2(g45.y, ya[r][5], acc);
                acc = ffma2(g67.x, ya[r][6], acc);
                acc = ffma2(g67.y, ya[r][7], acc);
                unsigned long long s2 = ffma2(TWO, acc, nn);

                float sp, sm;
                upk2(s2, sp, sm);
                if (sp > bsp[r]) { bsp[r] = sp; qp[r] = q; }
                if (sm > bsm[r]) { bsm[r] = sm; qm[r] = q; }
            }
            g01 = n01; g23 = n23; g45 = n45; g67 = n67; nn = nnn;
        }

        // Epilogue per row: direct residuals with reference rounding.
        #pragma unroll
        for (int r = 0; r < R; r++) {
            if (!valid[r]) continue;
            const unsigned mnegp = negp[r] ^ pp[r];   // parity flips bit 0
            const unsigned mnegm = negm[r] ^ pm[r];
            float e2p = 0.0f, e2m = 0.0f;
            #pragma unroll
            for (int j = 0; j < 8; j++) {
                float apj, amj;
                upk2(ya[r][j], apj, amj);
                float yp = ((negp[r] >> j) & 1u) ? -fabsf(apj) : fabsf(apj);
                float ym = ((negm[r] >> j) & 1u) ? -fabsf(amj) : fabsf(amj);
                float gp_ = sgf[qp[r] * 20 + j * 2];
                float gm_ = sgf[qm[r] * 20 + j * 2];
                float vpj = ((mnegp >> j) & 1u) ? -gp_ : gp_;
                float vmj = ((mnegm >> j) & 1u) ? -gm_ : gm_;
                float dp = __fsub_rn(yp, vpj);
                float dm = __fsub_rn(ym, vmj);
                e2p = __fadd_rn(e2p, __fmul_rn(dp, dp));
                e2m = __fadd_rn(e2m, __fmul_rn(dm, dm));
            }
            const bool which = __fsqrt_rn(e2p) < __fsqrt_rn(e2m);

            const int q = which ? qp[r] : qm[r];
            const unsigned mneg = which ? mnegp : mnegm;
            const float delta = which ? -0.25f : 0.25f;

            const int mint = (int)(__brev(mneg & 0xFFu) >> 24);  // bit j -> 2^(7-j)
            const int r128 = simap[mint];
            const int ridx = __ldg(&allcombo[(size_t)r128 * n_grid + q]);
            const int fidx = which ? ridx : (ridx - 32768);

            float v[8];
            #pragma unroll
            for (int j = 0; j < 8; j++) {
                float g = sgf[q * 20 + j * 2];
                float sg = ((mneg >> j) & 1u) ? -g : g;    // grid*mask (exact)
                v[j] = __fadd_rn(sg, delta);               // fl(vals -/+ 0.25)
            }
            float4* O = (float4*)(out + (size_t)rows[r] * 8);
            O[0] = make_float4(v[0], v[1], v[2], v[3]);
            O[1] = make_float4(v[4], v[5], v[6], v[7]);

            if (idx_mode == 1) {
                out[(size_t)N * 8 + rows[r]] = (float)fidx;
            } else if (idx_mode == 2) {
                ((short*)(out + (size_t)N * 8))[rows[r]] = (short)fidx;
            }
        }
    }
}

extern "C" void kernel_launch(void* const* d_in, const int* in_sizes, int n_in,
                              void* d_out, int out_size) {
    const float* X        = (const float*)d_in[0];
    const float* grid     = (const float*)d_in[1];
    const float* gnorm    = (const float*)d_in[2];
    const int*   allcombo = (const int*)d_in[3];
    const int*   idx_map  = (const int*)d_in[4];

    const int N = in_sizes[0] / 8;
    const int n_grid = in_sizes[2];

    int idx_mode = 0;
    if (out_size >= N * 9) idx_mode = 1;                     // idx stored as floats
    else if (out_size >= N * 8 + (N + 1) / 2) idx_mode = 2;  // idx packed as int16

    size_t smem_bytes = (size_t)(n_grid + 1) * 80 + 1024 + 64;
    cudaFuncSetAttribute(e8p_kernel, cudaFuncAttributeMaxDynamicSharedMemorySize,
                         (int)smem_bytes);

    init_counter_kernel<<<1, 1>>>();
    e8p_kernel<<<NCTAS, TPB, smem_bytes>>>(X, grid, gnorm, allcombo, idx_map,
                                           (float*)d_out, N, n_grid, idx_mode);
}

// round 7
// speedup vs baseline: 1.6527x; 1.4520x over previous
#include <cuda_runtime.h>
#include <cstdint>
#include <math_constants.h>

#define TPB 256
#define NCTAS 296

__device__ unsigned int g_counter;

__global__ void init_counter_kernel() { g_counter = 0u; }

__device__ __forceinline__ unsigned long long pk2(float lo, float hi) {
    unsigned long long r;
    asm("mov.b64 %0, {%1, %2};" : "=l"(r) : "f"(lo), "f"(hi));
    return r;
}
__device__ __forceinline__ void upk2(unsigned long long v, float& lo, float& hi) {
    asm("mov.b64 {%0, %1}, %2;" : "=f"(lo), "=f"(hi) : "l"(v));
}
// Packed fp32x2 FMA (Blackwell): per-lane IEEE rn FMA, identical rounding to scalar fmaf.
__device__ __forceinline__ unsigned long long ffma2(unsigned long long a,
                                                    unsigned long long b,
                                                    unsigned long long c) {
    unsigned long long d;
    asm("fma.rn.f32x2 %0, %1, %2, %3;" : "=l"(d) : "l"(a), "l"(b), "l"(c));
    return d;
}

__global__ __launch_bounds__(TPB, 2) void e8p_kernel(
    const float* __restrict__ X,
    const float* __restrict__ grid,       // [n_grid, 8]
    const float* __restrict__ gnorm,      // [n_grid]
    const int*   __restrict__ allcombo,   // [128, n_grid]
    const int*   __restrict__ idx_map,    // [256]
    float* __restrict__ out,
    int N, int n_grid, int ngp, int idx_mode)
{
    // Candidate record: 5 ulonglong2 = 80 B:
    //   [0..3] = (g0,g0),(g1,g1) | (g2,g2),(g3,g3) | (g4,g4),(g5,g5) | (g6,g6),(g7,g7)
    //   [4].x  = (-norm,-norm). Records q >= n_grid are sentinels: g=0, nn=-inf
    //   so their score is exactly -inf and can never win.
    extern __shared__ ulonglong2 srec[];
    int* simap = (int*)(srec + (size_t)ngp * 5);   // [256]

    for (int q = threadIdx.x; q < ngp; q += TPB) {
        ulonglong2* rrec = srec + (size_t)q * 5;
        if (q < n_grid) {
            const float* g = grid + (size_t)q * 8;
            #pragma unroll
            for (int p = 0; p < 4; p++)
                rrec[p] = make_ulonglong2(pk2(g[2 * p], g[2 * p]),
                                          pk2(g[2 * p + 1], g[2 * p + 1]));
            float nn = -gnorm[q];
            rrec[4] = make_ulonglong2(pk2(nn, nn), 0ull);
        } else {
            #pragma unroll
            for (int p = 0; p < 4; p++) rrec[p] = make_ulonglong2(0ull, 0ull);
            rrec[4] = make_ulonglong2(pk2(-CUDART_INF_F, -CUDART_INF_F), 0ull);
        }
    }
    if (threadIdx.x < 256) simap[threadIdx.x] = idx_map[threadIdx.x];
    __syncthreads();

    const int nchunks = N >> 6;          // 64 rows per chunk (2 per lane)
    const int lane = threadIdx.x & 31;
    const unsigned long long ZERO = pk2(0.0f, 0.0f);
    const unsigned long long TWO  = pk2(2.0f, 2.0f);
    const float* sgf = (const float*)srec;   // g_j of candidate q at sgf[q*20 + j*2]

    while (true) {
        unsigned c;
        if (lane == 0) c = atomicAdd(&g_counter, 1u);
        c = __shfl_sync(0xFFFFFFFFu, c, 0);
        if (c >= (unsigned)nchunks) break;
        const int base = (int)(c << 6);
        int rows[2] = {base + lane, base + 32 + lane};

        unsigned negp[2], negm[2], pp[2], pm[2];
        unsigned long long ya[2][8];

        #pragma unroll
        for (int r = 0; r < 2; r++) {
            const float4* X4 = (const float4*)(X + (size_t)rows[r] * 8);
            float4 xa = X4[0], xb = X4[1];
            float xr[8] = {xa.x, xa.y, xa.z, xa.w, xb.x, xb.y, xb.z, xb.w};

            unsigned np = 0u, nm = 0u;
            float ap[8], am[8];
            #pragma unroll
            for (int j = 0; j < 8; j++) {
                float yp = __fadd_rn(xr[j], 0.25f);
                float ym = __fsub_rn(xr[j], 0.25f);
                if (yp < 0.0f) np |= 1u << j;
                if (ym < 0.0f) nm |= 1u << j;
                ap[j] = fabsf(yp);
                am[j] = fabsf(ym);
            }
            pp[r] = __popc(np) & 1u;
            pm[r] = __popc(nm) & 1u;
            negp[r] = np; negm[r] = nm;
            if (pp[r]) ap[0] = -ap[0];
            if (pm[r]) am[0] = -am[0];
            #pragma unroll
            for (int j = 0; j < 8; j++) ya[r][j] = pk2(ap[j], am[j]);
        }

        // Dual (even/odd) best-trackers per score stream to halve the serial
        // FSETP/SEL loop-carried chain. A = even q, B = odd q.
        float bspA[2], bspB[2], bsmA[2], bsmB[2];
        int qpA[2], qpB[2], qmA[2], qmB[2];
        #pragma unroll
        for (int r = 0; r < 2; r++) {
            bspA[r] = bspB[r] = bsmA[r] = bsmB[r] = -CUDART_INF_F;
            qpA[r] = qpB[r] = qmA[r] = qmB[r] = 0;
        }

        for (int q = 0; q < ngp; q += 2) {
            const ulonglong2* g0 = srec + (size_t)q * 5;
            ulonglong2 a01 = g0[0], a23 = g0[1], a45 = g0[2], a67 = g0[3];
            unsigned long long nnA = g0[4].x;
            const ulonglong2* g1 = g0 + 5;
            ulonglong2 b01 = g1[0], b23 = g1[1], b45 = g1[2], b67 = g1[3];
            unsigned long long nnB = g1[4].x;

            #pragma unroll
            for (int r = 0; r < 2; r++) {
                unsigned long long accA = ffma2(a01.x, ya[r][0], ZERO);
                accA = ffma2(a01.y, ya[r][1], accA);
                accA = ffma2(a23.x, ya[r][2], accA);
                accA = ffma2(a23.y, ya[r][3], accA);
                accA = ffma2(a45.x, ya[r][4], accA);
                accA = ffma2(a45.y, ya[r][5], accA);
                accA = ffma2(a67.x, ya[r][6], accA);
                accA = ffma2(a67.y, ya[r][7], accA);
                unsigned long long sA = ffma2(TWO, accA, nnA);

                unsigned long long accB = ffma2(b01.x, ya[r][0], ZERO);
                accB = ffma2(b01.y, ya[r][1], accB);
                accB = ffma2(b23.x, ya[r][2], accB);
                accB = ffma2(b23.y, ya[r][3], accB);
                accB = ffma2(b45.x, ya[r][4], accB);
                accB = ffma2(b45.y, ya[r][5], accB);
                accB = ffma2(b67.x, ya[r][6], accB);
                accB = ffma2(b67.y, ya[r][7], accB);
                unsigned long long sB = ffma2(TWO, accB, nnB);

                float spA, smA, spB, smB;
                upk2(sA, spA, smA);
                upk2(sB, spB, smB);
                if (spA > bspA[r]) { bspA[r] = spA; qpA[r] = q; }
                if (smA > bsmA[r]) { bsmA[r] = smA; qmA[r] = q; }
                if (spB > bspB[r]) { bspB[r] = spB; qpB[r] = q + 1; }
                if (smB > bsmB[r]) { bsmB[r] = smB; qmB[r] = q + 1; }
            }
        }

        // Epilogue per row: merge trackers (exact first-max-wins), residual compare.
        #pragma unroll
        for (int r = 0; r < 2; r++) {
            float bsp; int qp;
            if (bspB[r] > bspA[r] || (bspB[r] == bspA[r] && qpB[r] < qpA[r])) {
                bsp = bspB[r]; qp = qpB[r];
            } else { bsp = bspA[r]; qp = qpA[r]; }
            float bsm; int qm;
            if (bsmB[r] > bsmA[r] || (bsmB[r] == bsmA[r] && qmB[r] < qmA[r])) {
                bsm = bsmB[r]; qm = qmB[r];
            } else { bsm = bsmA[r]; qm = qmA[r]; }
            (void)bsp; (void)bsm;

            const unsigned mnegp = negp[r] ^ pp[r];   // parity flips bit 0
            const unsigned mnegm = negm[r] ^ pm[r];
            float e2p = 0.0f, e2m = 0.0f;
            #pragma unroll
            for (int j = 0; j < 8; j++) {
                float apj, amj;
                upk2(ya[r][j], apj, amj);
                float yp = ((negp[r] >> j) & 1u) ? -fabsf(apj) : fabsf(apj);
                float ym = ((negm[r] >> j) & 1u) ? -fabsf(amj) : fabsf(amj);
                float gp_ = sgf[qp * 20 + j * 2];
                float gm_ = sgf[qm * 20 + j * 2];
                float vpj = ((mnegp >> j) & 1u) ? -gp_ : gp_;
                float vmj = ((mnegm >> j) & 1u) ? -gm_ : gm_;
                float dp = __fsub_rn(yp, vpj);
                float dm = __fsub_rn(ym, vmj);
                e2p = __fadd_rn(e2p, __fmul_rn(dp, dp));
                e2m = __fadd_rn(e2m, __fmul_rn(dm, dm));
            }
            const bool which = __fsqrt_rn(e2p) < __fsqrt_rn(e2m);

            const int q = which ? qp : qm;
            const unsigned mneg = which ? mnegp : mnegm;
            const float delta = which ? -0.25f : 0.25f;

            const int mint = (int)(__brev(mneg & 0xFFu) >> 24);  // bit j -> 2^(7-j)
            const int r128 = simap[mint];
            const int ridx = __ldg(&allcombo[(size_t)r128 * n_grid + q]);
            const int fidx = which ? ridx : (ridx - 32768);

            float v[8];
            #pragma unroll
            for (int j = 0; j < 8; j++) {
                float g = sgf[q * 20 + j * 2];
                float sg = ((mneg >> j) & 1u) ? -g : g;    // grid*mask (exact)
                v[j] = __fadd_rn(sg, delta);               // fl(vals -/+ 0.25)
            }
            float4* O = (float4*)(out + (size_t)rows[r] * 8);
            O[0] = make_float4(v[0], v[1], v[2], v[3]);
            O[1] = make_float4(v[4], v[5], v[6], v[7]);

            if (idx_mode == 1) {
                out[(size_t)N * 8 + rows[r]] = (float)fidx;
            } else if (idx_mode == 2) {
                ((short*)(out + (size_t)N * 8))[rows[r]] = (short)fidx;
            }
        }
    }
}

extern "C" void kernel_launch(void* const* d_in, const int* in_sizes, int n_in,
                              void* d_out, int out_size) {
    const float* X        = (const float*)d_in[0];
    const float* grid     = (const float*)d_in[1];
    const float* gnorm    = (const float*)d_in[2];
    const int*   allcombo = (const int*)d_in[3];
    const int*   idx_map  = (const int*)d_in[4];

    const int N = in_sizes[0] / 8;
    const int n_grid = in_sizes[2];
    const int ngp = (n_grid + 1) & ~1;       // pad to even with sentinel

    int idx_mode = 0;
    if (out_size >= N * 9) idx_mode = 1;                     // idx stored as floats
    else if (out_size >= N * 8 + (N + 1) / 2) idx_mode = 2;  // idx packed as int16

    size_t smem_bytes = (size_t)ngp * 80 + 1024 + 64;
    cudaFuncSetAttribute(e8p_kernel, cudaFuncAttributeMaxDynamicSharedMemorySize,
                         (int)smem_bytes);

    init_counter_kernel<<<1, 1>>>();
    e8p_kernel<<<NCTAS, TPB, smem_bytes>>>(X, grid, gnorm, allcombo, idx_map,
                                           (float*)d_out, N, n_grid, ngp, idx_mode);
}